// round 1
// baseline (speedup 1.0000x reference)
#include <cuda_runtime.h>

// Loss collapses to: M = count(pixels where trunc-index(r) != trunc-index(t));
// loss = M/(999*N) + M/N, with N = total pixels.
// Single kernel: grid-stride count -> block reduce -> global atomic ->
// last block (ticket) computes scalar, writes d_out, resets state so the
// kernel is deterministic across CUDA-graph replays.

__device__ unsigned int g_count = 0;   // running mismatch count
__device__ unsigned int g_ticket = 0;  // blocks-done ticket

static __device__ __forceinline__ int quant_idx(float x) {
    // match: x*1000 - 1, clamp below at 0, truncate to int (value in [0,999))
    float v = __fsub_rn(__fmul_rn(x, 1000.0f), 1.0f);
    v = v < 0.0f ? 0.0f : v;
    return (int)v;  // truncation == floor for non-negative v
}

__global__ void true3d_loss_kernel(const float* __restrict__ r,
                                   const float* __restrict__ t,
                                   float* __restrict__ out, int N) {
    const int tid = blockIdx.x * blockDim.x + threadIdx.x;
    const int stride = gridDim.x * blockDim.x;
    const int N4 = N >> 2;

    const float4* __restrict__ r4 = (const float4*)r;
    const float4* __restrict__ t4 = (const float4*)t;

    unsigned int cnt = 0;
    for (int i = tid; i < N4; i += stride) {
        float4 a = __ldg(&r4[i]);
        float4 b = __ldg(&t4[i]);
        cnt += (quant_idx(a.x) != quant_idx(b.x));
        cnt += (quant_idx(a.y) != quant_idx(b.y));
        cnt += (quant_idx(a.z) != quant_idx(b.z));
        cnt += (quant_idx(a.w) != quant_idx(b.w));
    }
    // scalar tail (N not multiple of 4)
    for (int i = (N4 << 2) + tid; i < N; i += stride) {
        cnt += (quant_idx(__ldg(&r[i])) != quant_idx(__ldg(&t[i])));
    }

    // warp reduce
    #pragma unroll
    for (int off = 16; off > 0; off >>= 1)
        cnt += __shfl_down_sync(0xFFFFFFFFu, cnt, off);

    // block reduce
    __shared__ unsigned int s_part[32];
    const int lane = threadIdx.x & 31;
    const int wid  = threadIdx.x >> 5;
    if (lane == 0) s_part[wid] = cnt;
    __syncthreads();
    const int nwarps = (blockDim.x + 31) >> 5;
    if (wid == 0) {
        unsigned int v = (lane < nwarps) ? s_part[lane] : 0u;
        #pragma unroll
        for (int off = 16; off > 0; off >>= 1)
            v += __shfl_down_sync(0xFFFFFFFFu, v, off);
        if (lane == 0) {
            atomicAdd(&g_count, v);
            __threadfence();
            unsigned int ticket = atomicAdd(&g_ticket, 1u);
            if (ticket == gridDim.x - 1) {
                // last block: read total, emit loss, reset for next replay
                unsigned int M = atomicExch(&g_count, 0u);
                float fM = (float)M;
                float n_nonzero = (float)N;             // one hot per pixel
                float n_zero = (float)N * 999.0f;       // N*1000 - N
                float loss = fM / n_zero + fM / n_nonzero;
                out[0] = loss;
                atomicExch(&g_ticket, 0u);
                __threadfence();
            }
        }
    }
}

extern "C" void kernel_launch(void* const* d_in, const int* in_sizes, int n_in,
                              void* d_out, int out_size) {
    const float* rec = (const float*)d_in[0];
    const float* tgt = (const float*)d_in[1];
    float* out = (float*)d_out;
    const int N = in_sizes[0];

    const int threads = 256;
    int blocks = (N / 4 + threads - 1) / threads;  // ~88 for N=90112
    if (blocks < 1) blocks = 1;
    if (blocks > 1024) blocks = 1024;

    true3d_loss_kernel<<<blocks, threads>>>(rec, tgt, out, N);
}

// round 2
// speedup vs baseline: 1.1923x; 1.1923x over previous
#include <cuda_runtime.h>

// Loss collapses to: M = count(pixels where trunc-index(r) != trunc-index(t));
// loss = M/(999*N) + M/N, with N = total pixels.
//
// Latency-optimized finalize: a single fused 64-bit atomic carries
// (partial_count << 32 | 1). The block whose add makes the low field hit
// gridDim.x is last; its returned old value + own contribution IS the total —
// no threadfence, no second ticket atomic. It writes the scalar and resets
// the accumulator for the next graph replay (deterministic across replays).

__device__ unsigned long long g_acc = 0ull;  // [count:32 | blocks_done:32]

static __device__ __forceinline__ int quant_idx(float x) {
    // match reference: x*1000 - 1, clamp below at 0, truncate (floor for v>=0)
    float v = __fsub_rn(__fmul_rn(x, 1000.0f), 1.0f);
    v = v < 0.0f ? 0.0f : v;
    return (int)v;
}

__global__ void true3d_loss_kernel(const float* __restrict__ r,
                                   const float* __restrict__ t,
                                   float* __restrict__ out, int N) {
    const int tid = blockIdx.x * blockDim.x + threadIdx.x;
    const int stride = gridDim.x * blockDim.x;
    const int N4 = N >> 2;

    const float4* __restrict__ r4 = (const float4*)r;
    const float4* __restrict__ t4 = (const float4*)t;

    unsigned int cnt = 0;
    for (int i = tid; i < N4; i += stride) {
        float4 a = __ldg(&r4[i]);
        float4 b = __ldg(&t4[i]);
        cnt += (quant_idx(a.x) != quant_idx(b.x));
        cnt += (quant_idx(a.y) != quant_idx(b.y));
        cnt += (quant_idx(a.z) != quant_idx(b.z));
        cnt += (quant_idx(a.w) != quant_idx(b.w));
    }
    for (int i = (N4 << 2) + tid; i < N; i += stride) {
        cnt += (quant_idx(__ldg(&r[i])) != quant_idx(__ldg(&t[i])));
    }

    // warp reduce: single REDUX instruction instead of 5-deep SHFL chain
    cnt = __reduce_add_sync(0xFFFFFFFFu, cnt);

    // block reduce
    __shared__ unsigned int s_part[32];
    const int lane = threadIdx.x & 31;
    const int wid  = threadIdx.x >> 5;
    if (lane == 0) s_part[wid] = cnt;
    __syncthreads();

    if (wid == 0) {
        const int nwarps = (blockDim.x + 31) >> 5;
        unsigned int v = (lane < nwarps) ? s_part[lane] : 0u;
        v = __reduce_add_sync(0xFFFFFFFFu, v);
        if (lane == 0) {
            // fused count+done atomic: count in high 32, done-blocks in low 32
            unsigned long long old =
                atomicAdd(&g_acc, ((unsigned long long)v << 32) | 1ull);
            if ((unsigned int)(old & 0xFFFFFFFFull) == gridDim.x - 1) {
                unsigned int M = (unsigned int)(old >> 32) + v;
                float fM = (float)M;
                float n_nonzero = (float)N;
                float n_zero = (float)N * 999.0f;
                out[0] = fM / n_zero + fM / n_nonzero;
                atomicExch(&g_acc, 0ull);  // reset for next graph replay
            }
        }
    }
}

extern "C" void kernel_launch(void* const* d_in, const int* in_sizes, int n_in,
                              void* d_out, int out_size) {
    const float* rec = (const float*)d_in[0];
    const float* tgt = (const float*)d_in[1];
    float* out = (float*)d_out;
    const int N = in_sizes[0];

    const int threads = 256;
    int blocks = (N / 4 + threads - 1) / threads;  // 88 for N=90112 (exact fit)
    if (blocks < 1) blocks = 1;
    if (blocks > 1024) blocks = 1024;

    true3d_loss_kernel<<<blocks, threads>>>(rec, tgt, out, N);
}